// round 1
// baseline (speedup 1.0000x reference)
#include <cuda_runtime.h>
#include <math.h>

#define LREF 384
#define DPC 128
#define HN 4
#define DHD 32
#define KTOT (LREF*DHD)   // 12288

// ---------------- scratch (device globals; no allocations allowed) ----------
__device__ float g_q[(size_t)HN*LREF*LREF*DHD];   // [h][i][n][d]
__device__ float g_k[(size_t)HN*LREF*LREF*DHD];   // [h][j][n][d]
__device__ float g_v[(size_t)HN*LREF*LREF*DHD];   // [h][n][j][d]
__device__ float g_gate[(size_t)LREF*LREF*DPC];   // [n][i][c]
__device__ float g_om[(size_t)LREF*LREF*DPC];     // [n][i][h*32+d]
__device__ float g_attn[(size_t)HN*LREF*LREF];    // [h][i][j]

// Compute, for 16 rows staged in smem, column t of rows @ W^T (W row-major [128 out][128 in])
__device__ __forceinline__ void matcol16(const float (*sx)[DPC], const float* __restrict__ W,
                                         int t, float* acc)
{
#pragma unroll
    for (int r = 0; r < 16; r++) acc[r] = 0.f;
    const float* wrow = W + (size_t)t * DPC;
    for (int c0 = 0; c0 < DPC; c0 += 32) {
        float w[32];
#pragma unroll
        for (int cc = 0; cc < 32; cc += 4) {
            float4 ww = *(const float4*)(wrow + c0 + cc);
            w[cc] = ww.x; w[cc+1] = ww.y; w[cc+2] = ww.z; w[cc+3] = ww.w;
        }
#pragma unroll
        for (int r = 0; r < 16; r++) {
            float a = acc[r];
#pragma unroll
            for (int cc = 0; cc < 32; cc += 4) {
                float4 xv = *(const float4*)(&sx[r][c0 + cc]);
                a += xv.x * w[cc];
                a += xv.y * w[cc+1];
                a += xv.z * w[cc+2];
                a += xv.w * w[cc+3];
            }
            acc[r] = a;
        }
    }
}

// -------- kernel A: LN(pair rows) + q/k/v/gate projections -------------------
__global__ __launch_bounds__(128) void proj_kernel(
    const float* __restrict__ pair, const float* __restrict__ lng, const float* __restrict__ lnb,
    const float* __restrict__ Wq, const float* __restrict__ Wk, const float* __restrict__ Wv,
    const float* __restrict__ Wg, const float* __restrict__ bg)
{
    __shared__ float sx[16][DPC];
    int tid = threadIdx.x, warp = tid >> 5, lane = tid & 31;
    int row0 = blockIdx.x * 16;                 // row = n*L + i

    for (int rr = 0; rr < 4; rr++) {
        int r = warp * 4 + rr;
        int row = row0 + r;
        int n = row / LREF, i = row % LREF;
        const float* x = pair + ((size_t)i * LREF + n) * DPC;   // p[n,i] = pair[i,n]
        float v0 = x[lane], v1 = x[lane+32], v2 = x[lane+64], v3 = x[lane+96];
        float s = v0 + v1 + v2 + v3;
#pragma unroll
        for (int o = 16; o; o >>= 1) s += __shfl_xor_sync(0xffffffffu, s, o);
        float mean = s * (1.f / DPC);
        float d0 = v0-mean, d1 = v1-mean, d2 = v2-mean, d3 = v3-mean;
        float ss = d0*d0 + d1*d1 + d2*d2 + d3*d3;
#pragma unroll
        for (int o = 16; o; o >>= 1) ss += __shfl_xor_sync(0xffffffffu, ss, o);
        float rstd = rsqrtf(ss * (1.f / DPC) + 1e-5f);
        sx[r][lane]    = d0 * rstd * lng[lane]    + lnb[lane];
        sx[r][lane+32] = d1 * rstd * lng[lane+32] + lnb[lane+32];
        sx[r][lane+64] = d2 * rstd * lng[lane+64] + lnb[lane+64];
        sx[r][lane+96] = d3 * rstd * lng[lane+96] + lnb[lane+96];
    }
    __syncthreads();

    int h = tid >> 5;
    int d = tid & 31;
    float acc[16];

    // Q (scaled 1/sqrt(32))
    matcol16(sx, Wq, tid, acc);
#pragma unroll
    for (int r = 0; r < 16; r++) {
        int row = row0 + r; int n = row / LREF, i = row % LREF;
        g_q[(((size_t)h * LREF + i) * LREF + n) * DHD + d] = acc[r] * 0.17677669529663687f;
    }
    // K (scaled 1/L)
    matcol16(sx, Wk, tid, acc);
#pragma unroll
    for (int r = 0; r < 16; r++) {
        int row = row0 + r; int n = row / LREF, i = row % LREF;
        g_k[(((size_t)h * LREF + i) * LREF + n) * DHD + d] = acc[r] * (1.0f / LREF);
    }
    // V
    matcol16(sx, Wv, tid, acc);
#pragma unroll
    for (int r = 0; r < 16; r++) {
        int row = row0 + r; int n = row / LREF, i = row % LREF;
        g_v[(((size_t)h * LREF + n) * LREF + i) * DHD + d] = acc[r];
    }
    // Gate = sigmoid(p@Wg^T + bg)
    matcol16(sx, Wg, tid, acc);
    float bgt = bg[tid];
#pragma unroll
    for (int r = 0; r < 16; r++) {
        int row = row0 + r;
        float z = acc[r] + bgt;
        g_gate[(size_t)row * DPC + tid] = 1.f / (1.f + expf(-z));
    }
}

// -------- kernel B: LN(bias rows) @ Wb^T -> init attn with pairwise bias -----
__global__ __launch_bounds__(128) void bias_kernel(
    const float* __restrict__ bias, const float* __restrict__ lng, const float* __restrict__ lnb,
    const float* __restrict__ Wb)
{
    __shared__ float sx[16][DPC];
    int tid = threadIdx.x, warp = tid >> 5, lane = tid & 31;
    int row0 = blockIdx.x * 16;                 // row = i*L + j

    for (int rr = 0; rr < 4; rr++) {
        int r = warp * 4 + rr;
        int row = row0 + r;
        int i = row / LREF, j = row % LREF;
        const float* x = bias + ((size_t)j * LREF + i) * DPC;   // bsrc[i,j] = bias[j,i]
        float v0 = x[lane], v1 = x[lane+32], v2 = x[lane+64], v3 = x[lane+96];
        float s = v0 + v1 + v2 + v3;
#pragma unroll
        for (int o = 16; o; o >>= 1) s += __shfl_xor_sync(0xffffffffu, s, o);
        float mean = s * (1.f / DPC);
        float d0 = v0-mean, d1 = v1-mean, d2 = v2-mean, d3 = v3-mean;
        float ss = d0*d0 + d1*d1 + d2*d2 + d3*d3;
#pragma unroll
        for (int o = 16; o; o >>= 1) ss += __shfl_xor_sync(0xffffffffu, ss, o);
        float rstd = rsqrtf(ss * (1.f / DPC) + 1e-5f);
        sx[r][lane]    = d0 * rstd * lng[lane]    + lnb[lane];
        sx[r][lane+32] = d1 * rstd * lng[lane+32] + lnb[lane+32];
        sx[r][lane+64] = d2 * rstd * lng[lane+64] + lnb[lane+64];
        sx[r][lane+96] = d3 * rstd * lng[lane+96] + lnb[lane+96];
    }
    __syncthreads();

    if (tid < 64) {
        int r = tid >> 2, h = tid & 3;
        int row = row0 + r;
        int i = row / LREF, j = row % LREF;
        const float* wrow = Wb + h * DPC;
        float acc = 0.f;
#pragma unroll
        for (int c = 0; c < DPC; c += 4) {
            float4 xv = *(const float4*)(&sx[r][c]);
            float4 wv = *(const float4*)(wrow + c);
            acc += xv.x*wv.x + xv.y*wv.y + xv.z*wv.z + xv.w*wv.w;
        }
        g_attn[((size_t)h * LREF + i) * LREF + j] = acc;
    }
}

// -------- kernel C: attn[h][i][j] += sum_{n,d} q k  (NT GEMM, K=12288) -------
__global__ __launch_bounds__(256) void score_kernel()
{
    __shared__ float As[16][64];
    __shared__ float Bs[16][64];
    int h = blockIdx.z;
    int i0 = blockIdx.x * 64, j0 = blockIdx.y * 64;
    int tid = threadIdx.x;
    int tx = tid & 15, ty = tid >> 4;            // 16x16 threads, 4x4 micro-tile
    const float* Abase = g_q + ((size_t)h * LREF + i0) * KTOT;
    const float* Bbase = g_k + ((size_t)h * LREF + j0) * KTOT;
    int lr = tid >> 2;                           // tile row 0..63
    int lk = (tid & 3) * 4;                      // k offset 0..12

    float acc[4][4];
#pragma unroll
    for (int a = 0; a < 4; a++)
#pragma unroll
        for (int b = 0; b < 4; b++) acc[a][b] = 0.f;

    for (int k0 = 0; k0 < KTOT; k0 += 16) {
        float4 av = *(const float4*)(Abase + (size_t)lr * KTOT + k0 + lk);
        float4 bv = *(const float4*)(Bbase + (size_t)lr * KTOT + k0 + lk);
        __syncthreads();
        As[lk+0][lr] = av.x; As[lk+1][lr] = av.y; As[lk+2][lr] = av.z; As[lk+3][lr] = av.w;
        Bs[lk+0][lr] = bv.x; Bs[lk+1][lr] = bv.y; Bs[lk+2][lr] = bv.z; Bs[lk+3][lr] = bv.w;
        __syncthreads();
#pragma unroll
        for (int k = 0; k < 16; k++) {
            float4 a = *(const float4*)(&As[k][ty * 4]);
            float4 b = *(const float4*)(&Bs[k][tx * 4]);
            acc[0][0] += a.x*b.x; acc[0][1] += a.x*b.y; acc[0][2] += a.x*b.z; acc[0][3] += a.x*b.w;
            acc[1][0] += a.y*b.x; acc[1][1] += a.y*b.y; acc[1][2] += a.y*b.z; acc[1][3] += a.y*b.w;
            acc[2][0] += a.z*b.x; acc[2][1] += a.z*b.y; acc[2][2] += a.z*b.z; acc[2][3] += a.z*b.w;
            acc[3][0] += a.w*b.x; acc[3][1] += a.w*b.y; acc[3][2] += a.w*b.z; acc[3][3] += a.w*b.w;
        }
    }
#pragma unroll
    for (int ii = 0; ii < 4; ii++)
#pragma unroll
        for (int jj = 0; jj < 4; jj++) {
            size_t idx = ((size_t)h * LREF + (i0 + ty*4 + ii)) * LREF + (j0 + tx*4 + jj);
            g_attn[idx] += acc[ii][jj];
        }
}

// -------- softmax over j per (h,i) ------------------------------------------
__global__ __launch_bounds__(128) void softmax_kernel()
{
    int i = blockIdx.x, h = blockIdx.y;
    float* row = g_attn + ((size_t)h * LREF + i) * LREF;
    int tid = threadIdx.x, warp = tid >> 5, lane = tid & 31;
    __shared__ float smax[4], ssum[4];

    float a0 = row[tid], a1 = row[tid + 128], a2 = row[tid + 256];
    float m = fmaxf(a0, fmaxf(a1, a2));
#pragma unroll
    for (int o = 16; o; o >>= 1) m = fmaxf(m, __shfl_xor_sync(0xffffffffu, m, o));
    if (lane == 0) smax[warp] = m;
    __syncthreads();
    float M = fmaxf(fmaxf(smax[0], smax[1]), fmaxf(smax[2], smax[3]));

    float e0 = expf(a0 - M), e1 = expf(a1 - M), e2 = expf(a2 - M);
    float s = e0 + e1 + e2;
#pragma unroll
    for (int o = 16; o; o >>= 1) s += __shfl_xor_sync(0xffffffffu, s, o);
    if (lane == 0) ssum[warp] = s;
    __syncthreads();
    float S = ssum[0] + ssum[1] + ssum[2] + ssum[3];
    float inv = 1.f / S;
    row[tid] = e0 * inv; row[tid + 128] = e1 * inv; row[tid + 256] = e2 * inv;
}

// -------- kernel D: out[n][i][h*32+d] = sum_j attn[h][i][j] * v[h][n][j][d] --
__global__ __launch_bounds__(128) void av_kernel()
{
    __shared__ float As[32][64];   // [j][i]
    __shared__ float Bs[32][32];   // [j][d]
    int i0 = blockIdx.x * 64, n = blockIdx.y, h = blockIdx.z;
    int tid = threadIdx.x;
    int tx = tid & 7, ty = tid >> 3;             // 8 d-groups x 16 i-groups
    const float* Abase = g_attn + ((size_t)h * LREF + i0) * LREF;
    const float* Bbase = g_v + ((size_t)h * LREF + n) * LREF * DHD;

    int ar = tid >> 1;                // 0..63
    int akb = (tid & 1) * 16;         // 0 or 16
    int bj = tid >> 2;                // 0..31
    int bd = (tid & 3) * 4;           // 0..12

    float acc[4][4];
#pragma unroll
    for (int a = 0; a < 4; a++)
#pragma unroll
        for (int b = 0; b < 4; b++) acc[a][b] = 0.f;

    for (int k0 = 0; k0 < LREF; k0 += 32) {
        float4 a0 = *(const float4*)(Abase + (size_t)ar * LREF + k0 + akb + 0);
        float4 a1 = *(const float4*)(Abase + (size_t)ar * LREF + k0 + akb + 4);
        float4 a2 = *(const float4*)(Abase + (size_t)ar * LREF + k0 + akb + 8);
        float4 a3 = *(const float4*)(Abase + (size_t)ar * LREF + k0 + akb + 12);
        float4 b0 = *(const float4*)(Bbase + (size_t)(k0 + bj) * DHD + bd);
        float4 b1 = *(const float4*)(Bbase + (size_t)(k0 + bj) * DHD + bd + 16);
        __syncthreads();
        As[akb+0][ar] = a0.x; As[akb+1][ar] = a0.y; As[akb+2][ar] = a0.z; As[akb+3][ar] = a0.w;
        As[akb+4][ar] = a1.x; As[akb+5][ar] = a1.y; As[akb+6][ar] = a1.z; As[akb+7][ar] = a1.w;
        As[akb+8][ar] = a2.x; As[akb+9][ar] = a2.y; As[akb+10][ar] = a2.z; As[akb+11][ar] = a2.w;
        As[akb+12][ar] = a3.x; As[akb+13][ar] = a3.y; As[akb+14][ar] = a3.z; As[akb+15][ar] = a3.w;
        *(float4*)(&Bs[bj][bd])      = b0;
        *(float4*)(&Bs[bj][bd + 16]) = b1;
        __syncthreads();
#pragma unroll
        for (int k = 0; k < 32; k++) {
            float4 a = *(const float4*)(&As[k][ty * 4]);
            float4 b = *(const float4*)(&Bs[k][tx * 4]);
            acc[0][0] += a.x*b.x; acc[0][1] += a.x*b.y; acc[0][2] += a.x*b.z; acc[0][3] += a.x*b.w;
            acc[1][0] += a.y*b.x; acc[1][1] += a.y*b.y; acc[1][2] += a.y*b.z; acc[1][3] += a.y*b.w;
            acc[2][0] += a.z*b.x; acc[2][1] += a.z*b.y; acc[2][2] += a.z*b.z; acc[2][3] += a.z*b.w;
            acc[3][0] += a.w*b.x; acc[3][1] += a.w*b.y; acc[3][2] += a.w*b.z; acc[3][3] += a.w*b.w;
        }
    }
#pragma unroll
    for (int ii = 0; ii < 4; ii++)
#pragma unroll
        for (int jj = 0; jj < 4; jj++) {
            int i = i0 + ty*4 + ii;
            int d = tx*4 + jj;
            g_om[((size_t)n * LREF + i) * DPC + h * DHD + d] = acc[ii][jj];
        }
}

// -------- kernel E: y = (gate .* om) @ Wo^T + bo, write transposed -----------
__global__ __launch_bounds__(128) void out_kernel(
    const float* __restrict__ Wo, const float* __restrict__ bo, float* __restrict__ outp)
{
    __shared__ float sx[16][DPC];
    int tid = threadIdx.x;
    int row0 = blockIdx.x * 16;                  // row = n*L + i
#pragma unroll
    for (int r = 0; r < 16; r++) {
        size_t row = row0 + r;
        sx[r][tid] = g_gate[row * DPC + tid] * g_om[row * DPC + tid];
    }
    __syncthreads();
    float acc[16];
    matcol16(sx, Wo, tid, acc);
    float bc = bo[tid];
#pragma unroll
    for (int r = 0; r < 16; r++) {
        int row = row0 + r; int n = row / LREF, i = row % LREF;
        outp[((size_t)i * LREF + n) * DPC + tid] = acc[r] + bc;   // final transpose
    }
}

extern "C" void kernel_launch(void* const* d_in, const int* in_sizes, int n_in,
                              void* d_out, int out_size)
{
    (void)in_sizes; (void)n_in; (void)out_size;
    const float* pair      = (const float*)d_in[0];
    const float* bias      = (const float*)d_in[1];
    const float* ln_pair_g = (const float*)d_in[2];
    const float* ln_pair_b = (const float*)d_in[3];
    const float* ln_bias_g = (const float*)d_in[4];
    const float* ln_bias_b = (const float*)d_in[5];
    const float* Wq = (const float*)d_in[6];
    const float* Wk = (const float*)d_in[7];
    const float* Wv = (const float*)d_in[8];
    const float* Wb = (const float*)d_in[9];
    const float* Wg = (const float*)d_in[10];
    const float* bg = (const float*)d_in[11];
    const float* Wo = (const float*)d_in[12];
    const float* bo = (const float*)d_in[13];
    float* outp = (float*)d_out;

    int nb = LREF * LREF / 16;   // 9216
    proj_kernel<<<nb, 128>>>(pair, ln_pair_g, ln_pair_b, Wq, Wk, Wv, Wg, bg);
    bias_kernel<<<nb, 128>>>(bias, ln_bias_g, ln_bias_b, Wb);
    score_kernel<<<dim3(6, 6, HN), 256>>>();
    softmax_kernel<<<dim3(LREF, HN), 128>>>();
    av_kernel<<<dim3(6, LREF, HN), 128>>>();
    out_kernel<<<nb, 128>>>(Wo, bo, outp);
}

// round 2
// speedup vs baseline: 2.7345x; 2.7345x over previous
#include <cuda_runtime.h>
#include <math.h>

#define LREF 384
#define DPC 128
#define HN 4
#define DHD 32
#define KTOT (LREF*DHD)   // 12288

// ---------------- scratch (device globals; no allocations allowed) ----------
__device__ float g_q[(size_t)HN*LREF*KTOT];       // [h][i][n*32+d]  (tf32-rounded)
__device__ float g_k[(size_t)HN*LREF*KTOT];       // [h][j][n*32+d]  (tf32-rounded)
__device__ float g_v[(size_t)HN*KTOT*LREF];       // [h][n*32+d][j]  (tf32-rounded)
__device__ float g_gate[(size_t)LREF*LREF*DPC];   // [n][i][c]       (fp32)
__device__ float g_om[(size_t)LREF*LREF*DPC];     // [n][i][h*32+d]  (fp32)
__device__ float g_attn[(size_t)HN*LREF*LREF];    // [h][i][j]

// ---------------- helpers ----------------------------------------------------
__device__ __forceinline__ float tf32r(float f) {
    unsigned u; asm("cvt.rna.tf32.f32 %0, %1;" : "=r"(u) : "f"(f));
    return __uint_as_float(u);
}

__device__ __forceinline__ void mma_tf32(float c[4], const unsigned a[4], const unsigned b[2]) {
    asm volatile(
        "mma.sync.aligned.m16n8k8.row.col.f32.tf32.tf32.f32 "
        "{%0,%1,%2,%3},{%4,%5,%6,%7},{%8,%9},{%0,%1,%2,%3};\n"
        : "+f"(c[0]), "+f"(c[1]), "+f"(c[2]), "+f"(c[3])
        : "r"(a[0]), "r"(a[1]), "r"(a[2]), "r"(a[3]), "r"(b[0]), "r"(b[1]));
}

__device__ __forceinline__ void cpa16(unsigned saddr, const void* g) {
    asm volatile("cp.async.cg.shared.global [%0],[%1],16;\n" :: "r"(saddr), "l"(g));
}
__device__ __forceinline__ void cpa_commit() { asm volatile("cp.async.commit_group;\n"); }
template<int N>
__device__ __forceinline__ void cpa_wait() { asm volatile("cp.async.wait_group %0;\n" :: "n"(N)); }

// One k-step (k8) for a warp computing a 64x64 tile: 4 m-tiles x 8 n-tiles.
// As stride = ASTRIDE floats, Bs stride = 36 floats ([N][K] layout).
template<int ASTRIDE>
__device__ __forceinline__ void warp_mma_kstep(float acc[4][8][4],
    const float* As, const float* Bs, int aRow0, int bCol0, int aK, int bK, int lane)
{
    unsigned a[4][4];
#pragma unroll
    for (int mt = 0; mt < 4; mt++) {
        int r = aRow0 + mt*16 + (lane >> 2);
        int c = aK + (lane & 3);
        a[mt][0] = __float_as_uint(As[r*ASTRIDE + c]);
        a[mt][1] = __float_as_uint(As[(r+8)*ASTRIDE + c]);
        a[mt][2] = __float_as_uint(As[r*ASTRIDE + c + 4]);
        a[mt][3] = __float_as_uint(As[(r+8)*ASTRIDE + c + 4]);
    }
#pragma unroll
    for (int nt = 0; nt < 8; nt++) {
        int n = bCol0 + nt*8 + (lane >> 2);
        int c = bK + (lane & 3);
        unsigned b[2];
        b[0] = __float_as_uint(Bs[n*36 + c]);
        b[1] = __float_as_uint(Bs[n*36 + c + 4]);
#pragma unroll
        for (int mt = 0; mt < 4; mt++) mma_tf32(acc[mt][nt], a[mt], b);
    }
}

// -------- kernel A: LN(pair rows) + q/k/v/gate projections (tf32 MMA) --------
// 128 threads = 4 warps (2m x 2n, each 64x64). Mtile=128 rows, N=128 per matrix.
__global__ void __launch_bounds__(128) proj_kernel(
    const float* __restrict__ pair, const float* __restrict__ lng, const float* __restrict__ lnb,
    const float* __restrict__ Wq, const float* __restrict__ Wk, const float* __restrict__ Wv,
    const float* __restrict__ Wg, const float* __restrict__ bg)
{
    extern __shared__ float dsm[];
    float* sX = dsm;              // [128][132] tf32 LN'ed input
    float* sW = dsm + 128*132;    // [128][36]  tf32 weight chunk
    int tid = threadIdx.x, lane = tid & 31, warp = tid >> 5;
    int wm = warp & 1, wn = warp >> 1;
    int row0 = blockIdx.x * 128;

    // ---- LayerNorm: one thread per row (rows are p[n,i] = pair[i,n]) ----
    {
        int r = tid;
        int row = row0 + r;
        int n = row / LREF, i = row - n*LREF;
        const float* x = pair + ((size_t)i*LREF + n) * DPC;
        float s = 0.f, s2 = 0.f;
#pragma unroll 8
        for (int c = 0; c < DPC; c += 4) {
            float4 t = *(const float4*)(x + c);
            s  += t.x + t.y + t.z + t.w;
            s2 += t.x*t.x + t.y*t.y + t.z*t.z + t.w*t.w;
        }
        float mean = s * (1.f/DPC);
        float var  = s2 * (1.f/DPC) - mean*mean;
        float rstd = rsqrtf(var + 1e-5f);
#pragma unroll 8
        for (int c = 0; c < DPC; c += 4) {
            float4 t = *(const float4*)(x + c);
            float4 o;
            o.x = tf32r((t.x-mean)*rstd*lng[c+0] + lnb[c+0]);
            o.y = tf32r((t.y-mean)*rstd*lng[c+1] + lnb[c+1]);
            o.z = tf32r((t.z-mean)*rstd*lng[c+2] + lnb[c+2]);
            o.w = tf32r((t.w-mean)*rstd*lng[c+3] + lnb[c+3]);
            *(float4*)&sX[r*132 + c] = o;
        }
    }
    __syncthreads();

    const float* Ws[4] = { Wq, Wk, Wv, Wg };
    for (int mat = 0; mat < 4; mat++) {
        float acc[4][8][4];
#pragma unroll
        for (int a = 0; a < 4; a++)
#pragma unroll
            for (int b = 0; b < 8; b++)
#pragma unroll
                for (int cc = 0; cc < 4; cc++) acc[a][b][cc] = 0.f;

        const float* W = Ws[mat];
        for (int kc = 0; kc < 4; kc++) {
            __syncthreads();
            // stage W chunk: rows n=0..127, cols kc*32..+32
            for (int idx = tid; idx < 1024; idx += 128) {
                int n = idx >> 3, q = idx & 7;
                float4 t = *(const float4*)(W + (size_t)n*DPC + kc*32 + q*4);
                float4 o; o.x = tf32r(t.x); o.y = tf32r(t.y); o.z = tf32r(t.z); o.w = tf32r(t.w);
                *(float4*)&sW[n*36 + q*4] = o;
            }
            __syncthreads();
#pragma unroll
            for (int kk = 0; kk < 4; kk++)
                warp_mma_kstep<132>(acc, sX, sW, wm*64, wn*64, kc*32 + kk*8, kk*8, lane);
        }

        // ---- epilogue per matrix ----
#pragma unroll
        for (int mt = 0; mt < 4; mt++)
#pragma unroll
            for (int nt = 0; nt < 8; nt++) {
                float* ac = acc[mt][nt];
                int rl = wm*64 + mt*16 + (lane >> 2);
                int c  = wn*64 + nt*8 + 2*(lane & 3);
#pragma unroll
                for (int half = 0; half < 2; half++) {
                    int row = row0 + rl + half*8;
                    float v0 = ac[half*2+0], v1 = ac[half*2+1];
                    int n = row / LREF, i = row - n*LREF;
                    int h = c >> 5, d = c & 31;
                    if (mat == 0) {        // q: scale 1/sqrt(32), layout [h][i][n*32+d]
                        float2 o = make_float2(tf32r(v0*0.17677669529663687f),
                                               tf32r(v1*0.17677669529663687f));
                        *(float2*)&g_q[((size_t)(h*LREF + i))*KTOT + n*DHD + d] = o;
                    } else if (mat == 1) { // k: scale 1/L
                        float2 o = make_float2(tf32r(v0*(1.0f/LREF)), tf32r(v1*(1.0f/LREF)));
                        *(float2*)&g_k[((size_t)(h*LREF + i))*KTOT + n*DHD + d] = o;
                    } else if (mat == 2) { // v: layout [h][n*32+d][j=i]
                        g_v[((size_t)h*KTOT + n*DHD + d)  *LREF + i] = tf32r(v0);
                        g_v[((size_t)h*KTOT + n*DHD + d+1)*LREF + i] = tf32r(v1);
                    } else {               // gate = sigmoid(. + bg)
                        float z0 = v0 + bg[c], z1 = v1 + bg[c+1];
                        float2 o = make_float2(1.f/(1.f+expf(-z0)), 1.f/(1.f+expf(-z1)));
                        *(float2*)&g_gate[(size_t)row*DPC + c] = o;
                    }
                }
            }
    }
}

// -------- kernel B: LN(bias rows) @ Wb^T -> init attn with pairwise bias -----
__global__ void __launch_bounds__(128) bias_kernel(
    const float* __restrict__ bias, const float* __restrict__ lng, const float* __restrict__ lnb,
    const float* __restrict__ Wb)
{
    __shared__ float sx[16][DPC];
    int tid = threadIdx.x, warp = tid >> 5, lane = tid & 31;
    int row0 = blockIdx.x * 16;                 // row = i*L + j

    for (int rr = 0; rr < 4; rr++) {
        int r = warp * 4 + rr;
        int row = row0 + r;
        int i = row / LREF, j = row % LREF;
        const float* x = bias + ((size_t)j * LREF + i) * DPC;   // bsrc[i,j] = bias[j,i]
        float v0 = x[lane], v1 = x[lane+32], v2 = x[lane+64], v3 = x[lane+96];
        float s = v0 + v1 + v2 + v3;
#pragma unroll
        for (int o = 16; o; o >>= 1) s += __shfl_xor_sync(0xffffffffu, s, o);
        float mean = s * (1.f / DPC);
        float d0 = v0-mean, d1 = v1-mean, d2 = v2-mean, d3 = v3-mean;
        float ss = d0*d0 + d1*d1 + d2*d2 + d3*d3;
#pragma unroll
        for (int o = 16; o; o >>= 1) ss += __shfl_xor_sync(0xffffffffu, ss, o);
        float rstd = rsqrtf(ss * (1.f / DPC) + 1e-5f);
        sx[r][lane]    = d0 * rstd * lng[lane]    + lnb[lane];
        sx[r][lane+32] = d1 * rstd * lng[lane+32] + lnb[lane+32];
        sx[r][lane+64] = d2 * rstd * lng[lane+64] + lnb[lane+64];
        sx[r][lane+96] = d3 * rstd * lng[lane+96] + lnb[lane+96];
    }
    __syncthreads();

    if (tid < 64) {
        int r = tid >> 2, h = tid & 3;
        int row = row0 + r;
        int i = row / LREF, j = row % LREF;
        const float* wrow = Wb + h * DPC;
        float acc = 0.f;
#pragma unroll
        for (int c = 0; c < DPC; c += 4) {
            float4 xv = *(const float4*)(&sx[r][c]);
            float4 wv = *(const float4*)(wrow + c);
            acc += xv.x*wv.x + xv.y*wv.y + xv.z*wv.z + xv.w*wv.w;
        }
        g_attn[((size_t)h * LREF + i) * LREF + j] = acc;
    }
}

// -------- kernel C: scores attn[h][i][j] += q.k  (128x128 tiles, split-K 4) --
__global__ void __launch_bounds__(128) score_kernel()
{
    extern __shared__ float dsm[];
    float* As = dsm;                 // [2][128*36]
    float* Bs = dsm + 2*128*36;      // [2][128*36]
    int tid = threadIdx.x, lane = tid & 31, warp = tid >> 5;
    int wm = warp & 1, wn = warp >> 1;
    int h = blockIdx.z >> 2, ks = blockIdx.z & 3;
    int i0 = blockIdx.x * 128, j0 = blockIdx.y * 128;
    int kbase = ks * (KTOT/4);

    const float* ga = g_q + ((size_t)(h*LREF + i0 + tid))*KTOT + kbase;
    const float* gb = g_k + ((size_t)(h*LREF + j0 + tid))*KTOT + kbase;
    unsigned sa = (unsigned)__cvta_generic_to_shared(As + tid*36);
    unsigned sb = (unsigned)__cvta_generic_to_shared(Bs + tid*36);
    const unsigned BUFB = 128*36*4;

    float acc[4][8][4];
#pragma unroll
    for (int a = 0; a < 4; a++)
#pragma unroll
        for (int b = 0; b < 8; b++)
#pragma unroll
            for (int cc = 0; cc < 4; cc++) acc[a][b][cc] = 0.f;

    const int nIter = (KTOT/4)/32;   // 96
    // prologue stage
#pragma unroll
    for (int q = 0; q < 8; q++) { cpa16(sa + q*16, ga + q*4); cpa16(sb + q*16, gb + q*4); }
    cpa_commit();

    for (int it = 0; it < nIter; it++) {
        int nxt = it + 1;
        if (nxt < nIter) {
            unsigned off = (nxt & 1) * BUFB;
            const float* pa = ga + nxt*32;
            const float* pb = gb + nxt*32;
#pragma unroll
            for (int q = 0; q < 8; q++) { cpa16(sa + off + q*16, pa + q*4); cpa16(sb + off + q*16, pb + q*4); }
            cpa_commit();
            cpa_wait<1>();
        } else {
            cpa_wait<0>();
        }
        __syncthreads();
        const float* A = As + (it & 1) * 128*36;
        const float* B = Bs + (it & 1) * 128*36;
#pragma unroll
        for (int kk = 0; kk < 4; kk++)
            warp_mma_kstep<36>(acc, A, B, wm*64, wn*64, kk*8, kk*8, lane);
        __syncthreads();
    }

    // epilogue: atomic accumulate into bias-initialized g_attn
#pragma unroll
    for (int mt = 0; mt < 4; mt++)
#pragma unroll
        for (int nt = 0; nt < 8; nt++) {
            float* ac = acc[mt][nt];
            int r = i0 + wm*64 + mt*16 + (lane >> 2);
            int c = j0 + wn*64 + nt*8 + 2*(lane & 3);
            size_t base = ((size_t)h*LREF + r)*LREF + c;
            atomicAdd(&g_attn[base],            ac[0]);
            atomicAdd(&g_attn[base + 1],        ac[1]);
            atomicAdd(&g_attn[base + 8*LREF],   ac[2]);
            atomicAdd(&g_attn[base + 8*LREF+1], ac[3]);
        }
}

// -------- softmax over j per (h,i), store tf32-rounded ----------------------
__global__ void __launch_bounds__(128) softmax_kernel()
{
    int i = blockIdx.x, h = blockIdx.y;
    float* row = g_attn + ((size_t)h * LREF + i) * LREF;
    int tid = threadIdx.x, warp = tid >> 5, lane = tid & 31;
    __shared__ float smax[4], ssum[4];

    float a0 = row[tid], a1 = row[tid + 128], a2 = row[tid + 256];
    float m = fmaxf(a0, fmaxf(a1, a2));
#pragma unroll
    for (int o = 16; o; o >>= 1) m = fmaxf(m, __shfl_xor_sync(0xffffffffu, m, o));
    if (lane == 0) smax[warp] = m;
    __syncthreads();
    float M = fmaxf(fmaxf(smax[0], smax[1]), fmaxf(smax[2], smax[3]));

    float e0 = expf(a0 - M), e1 = expf(a1 - M), e2 = expf(a2 - M);
    float s = e0 + e1 + e2;
#pragma unroll
    for (int o = 16; o; o >>= 1) s += __shfl_xor_sync(0xffffffffu, s, o);
    if (lane == 0) ssum[warp] = s;
    __syncthreads();
    float S = ssum[0] + ssum[1] + ssum[2] + ssum[3];
    float inv = 1.f / S;
    row[tid]       = tf32r(e0 * inv);
    row[tid + 128] = tf32r(e1 * inv);
    row[tid + 256] = tf32r(e2 * inv);
}

// -------- kernel D: out[n][i][h*32+d] = attn[h] @ v[h]  (128x128 tiles) ------
__global__ void __launch_bounds__(128) av_kernel()
{
    extern __shared__ float dsm[];
    float* As = dsm;
    float* Bs = dsm + 2*128*36;
    int tid = threadIdx.x, lane = tid & 31, warp = tid >> 5;
    int wm = warp & 1, wn = warp >> 1;
    int i0 = blockIdx.x * 128;
    int col0 = blockIdx.y * 128;     // col = n*32+d
    int h = blockIdx.z;

    const float* ga = g_attn + ((size_t)(h*LREF + i0 + tid))*LREF;
    const float* gb = g_v    + ((size_t)h*KTOT + col0 + tid)*LREF;
    unsigned sa = (unsigned)__cvta_generic_to_shared(As + tid*36);
    unsigned sb = (unsigned)__cvta_generic_to_shared(Bs + tid*36);
    const unsigned BUFB = 128*36*4;

    float acc[4][8][4];
#pragma unroll
    for (int a = 0; a < 4; a++)
#pragma unroll
        for (int b = 0; b < 8; b++)
#pragma unroll
            for (int cc = 0; cc < 4; cc++) acc[a][b][cc] = 0.f;

    const int nIter = LREF/32;   // 12
#pragma unroll
    for (int q = 0; q < 8; q++) { cpa16(sa + q*16, ga + q*4); cpa16(sb + q*16, gb + q*4); }
    cpa_commit();

    for (int it = 0; it < nIter; it++) {
        int nxt = it + 1;
        if (nxt < nIter) {
            unsigned off = (nxt & 1) * BUFB;
            const float* pa = ga + nxt*32;
            const float* pb = gb + nxt*32;
#pragma unroll
            for (int q = 0; q < 8; q++) { cpa16(sa + off + q*16, pa + q*4); cpa16(sb + off + q*16, pb + q*4); }
            cpa_commit();
            cpa_wait<1>();
        } else {
            cpa_wait<0>();
        }
        __syncthreads();
        const float* A = As + (it & 1) * 128*36;
        const float* B = Bs + (it & 1) * 128*36;
#pragma unroll
        for (int kk = 0; kk < 4; kk++)
            warp_mma_kstep<36>(acc, A, B, wm*64, wn*64, kk*8, kk*8, lane);
        __syncthreads();
    }

#pragma unroll
    for (int mt = 0; mt < 4; mt++)
#pragma unroll
        for (int nt = 0; nt < 8; nt++) {
            float* ac = acc[mt][nt];
            int r = i0 + wm*64 + mt*16 + (lane >> 2);   // i index
            int c = col0 + wn*64 + nt*8 + 2*(lane & 3); // n*32+d
            int n = c >> 5, d = c & 31;
#pragma unroll
            for (int half = 0; half < 2; half++) {
                int i = r + half*8;
                float2 o = make_float2(ac[half*2+0], ac[half*2+1]);
                *(float2*)&g_om[((size_t)n*LREF + i)*DPC + h*DHD + d] = o;
            }
        }
}

// -------- kernel E: y = (gate .* om) @ Wo^T + bo, write transposed -----------
__global__ void __launch_bounds__(128) out_kernel(
    const float* __restrict__ Wo, const float* __restrict__ bo, float* __restrict__ outp)
{
    __shared__ float sX[128*36];
    __shared__ float sW[128*36];
    int tid = threadIdx.x, lane = tid & 31, warp = tid >> 5;
    int wm = warp & 1, wn = warp >> 1;
    int row0 = blockIdx.x * 128;

    float acc[4][8][4];
#pragma unroll
    for (int a = 0; a < 4; a++)
#pragma unroll
        for (int b = 0; b < 8; b++)
#pragma unroll
            for (int cc = 0; cc < 4; cc++) acc[a][b][cc] = 0.f;

    for (int kc = 0; kc < 4; kc++) {
        __syncthreads();
        for (int idx = tid; idx < 1024; idx += 128) {
            int r = idx >> 3, q = idx & 7;
            size_t off = (size_t)(row0 + r)*DPC + kc*32 + q*4;
            float4 gt = *(const float4*)&g_gate[off];
            float4 ot = *(const float4*)&g_om[off];
            float4 o;
            o.x = tf32r(gt.x*ot.x); o.y = tf32r(gt.y*ot.y);
            o.z = tf32r(gt.z*ot.z); o.w = tf32r(gt.w*ot.w);
            *(float4*)&sX[r*36 + q*4] = o;
        }
        for (int idx = tid; idx < 1024; idx += 128) {
            int n = idx >> 3, q = idx & 7;
            float4 t = *(const float4*)(Wo + (size_t)n*DPC + kc*32 + q*4);
            float4 o; o.x = tf32r(t.x); o.y = tf32r(t.y); o.z = tf32r(t.z); o.w = tf32r(t.w);
            *(float4*)&sW[n*36 + q*4] = o;
        }
        __syncthreads();
#pragma unroll
        for (int kk = 0; kk < 4; kk++)
            warp_mma_kstep<36>(acc, sX, sW, wm*64, wn*64, kk*8, kk*8, lane);
    }

#pragma unroll
    for (int mt = 0; mt < 4; mt++)
#pragma unroll
        for (int nt = 0; nt < 8; nt++) {
            float* ac = acc[mt][nt];
            int rl = wm*64 + mt*16 + (lane >> 2);
            int c  = wn*64 + nt*8 + 2*(lane & 3);
#pragma unroll
            for (int half = 0; half < 2; half++) {
                int row = row0 + rl + half*8;
                int n = row / LREF, i = row - n*LREF;
                float2 o = make_float2(ac[half*2+0] + bo[c], ac[half*2+1] + bo[c+1]);
                *(float2*)&outp[((size_t)i*LREF + n)*DPC + c] = o;
            }
        }
}

extern "C" void kernel_launch(void* const* d_in, const int* in_sizes, int n_in,
                              void* d_out, int out_size)
{
    (void)in_sizes; (void)n_in; (void)out_size;
    const float* pair      = (const float*)d_in[0];
    const float* bias      = (const float*)d_in[1];
    const float* ln_pair_g = (const float*)d_in[2];
    const float* ln_pair_b = (const float*)d_in[3];
    const float* ln_bias_g = (const float*)d_in[4];
    const float* ln_bias_b = (const float*)d_in[5];
    const float* Wq = (const float*)d_in[6];
    const float* Wk = (const float*)d_in[7];
    const float* Wv = (const float*)d_in[8];
    const float* Wb = (const float*)d_in[9];
    const float* Wg = (const float*)d_in[10];
    const float* bg = (const float*)d_in[11];
    const float* Wo = (const float*)d_in[12];
    const float* bo = (const float*)d_in[13];
    float* outp = (float*)d_out;

    const int PROJ_SMEM = (128*132 + 128*36) * 4;   // 86016
    const int GEMM_SMEM = (4*128*36) * 4;           // 73728
    cudaFuncSetAttribute(proj_kernel,  cudaFuncAttributeMaxDynamicSharedMemorySize, PROJ_SMEM);
    cudaFuncSetAttribute(score_kernel, cudaFuncAttributeMaxDynamicSharedMemorySize, GEMM_SMEM);
    cudaFuncSetAttribute(av_kernel,    cudaFuncAttributeMaxDynamicSharedMemorySize, GEMM_SMEM);

    proj_kernel<<<LREF*LREF/128, 128, PROJ_SMEM>>>(pair, ln_pair_g, ln_pair_b, Wq, Wk, Wv, Wg, bg);
    bias_kernel<<<LREF*LREF/16, 128>>>(bias, ln_bias_g, ln_bias_b, Wb);
    score_kernel<<<dim3(3, 3, 16), 128, GEMM_SMEM>>>();
    softmax_kernel<<<dim3(LREF, HN), 128>>>();
    av_kernel<<<dim3(3, 96, HN), 128, GEMM_SMEM>>>();
    out_kernel<<<LREF*LREF/128, 128>>>(Wo, bo, outp);
}

// round 3
// speedup vs baseline: 5.1614x; 1.8875x over previous
#include <cuda_runtime.h>
#include <cuda_bf16.h>
#include <math.h>

#define LREF 384
#define DPC 128
#define HN 4
#define DHD 32
#define KTOT (LREF*DHD)   // 12288

typedef __nv_bfloat16 bf16;
typedef __nv_bfloat162 bf162;

// ---------------- scratch (device globals) ----------------------------------
__device__ bf16 g_qb[(size_t)HN*LREF*KTOT];     // [h][i][n*32+d] K-major
__device__ bf16 g_kb[(size_t)HN*LREF*KTOT];     // [h][j][n*32+d] K-major
__device__ bf16 g_vb[(size_t)HN*LREF*KTOT];     // [h][j][n*32+d] (j rows, col-major via trans ldsm)
__device__ bf16 g_gateb[(size_t)LREF*LREF*DPC]; // [row=n*L+i][c]
__device__ bf16 g_omb[(size_t)LREF*LREF*DPC];   // [row=n*L+i][h*32+d]
__device__ float g_attn[(size_t)HN*LREF*LREF];  // fp32 logits (bias-init + atomics)
__device__ bf16 g_attnb[(size_t)HN*LREF*LREF];  // softmaxed, bf16

// ---------------- ptx helpers ------------------------------------------------
__device__ __forceinline__ void ldsm4(unsigned &r0,unsigned &r1,unsigned &r2,unsigned &r3,unsigned a){
    asm volatile("ldmatrix.sync.aligned.m8n8.x4.shared.b16 {%0,%1,%2,%3},[%4];"
        :"=r"(r0),"=r"(r1),"=r"(r2),"=r"(r3):"r"(a));
}
__device__ __forceinline__ void ldsm4t(unsigned &r0,unsigned &r1,unsigned &r2,unsigned &r3,unsigned a){
    asm volatile("ldmatrix.sync.aligned.m8n8.x4.trans.shared.b16 {%0,%1,%2,%3},[%4];"
        :"=r"(r0),"=r"(r1),"=r"(r2),"=r"(r3):"r"(a));
}
__device__ __forceinline__ void mma_bf16(float c[4], const unsigned a[4], const unsigned b[2]){
    asm volatile("mma.sync.aligned.m16n8k16.row.col.f32.bf16.bf16.f32 "
        "{%0,%1,%2,%3},{%4,%5,%6,%7},{%8,%9},{%0,%1,%2,%3};"
        :"+f"(c[0]),"+f"(c[1]),"+f"(c[2]),"+f"(c[3])
        :"r"(a[0]),"r"(a[1]),"r"(a[2]),"r"(a[3]),"r"(b[0]),"r"(b[1]));
}
__device__ __forceinline__ void cpa16(unsigned saddr, const void* g) {
    asm volatile("cp.async.cg.shared.global [%0],[%1],16;\n" :: "r"(saddr), "l"(g));
}
__device__ __forceinline__ void cpa_commit() { asm volatile("cp.async.commit_group;\n"); }
template<int N>
__device__ __forceinline__ void cpa_wait() { asm volatile("cp.async.wait_group %0;\n" :: "n"(N)); }

__device__ __forceinline__ unsigned pk2(float a, float b){
    bf162 t = __floats2bfloat162_rn(a, b);
    return *(unsigned*)&t;
}

// warp k16-step, A buffer 128B rows [m][k64], B buffer 128B rows [n][k64]
template<int MT,int NT>
__device__ __forceinline__ void wstep(float (&acc)[MT][NT][4], unsigned sA, unsigned sB,
                                      int m0, int n0, int k0, int lane)
{
    unsigned a[MT][4];
    int arow = lane & 15, acg = (k0>>3) + (lane>>4);
#pragma unroll
    for (int mt = 0; mt < MT; mt++) {
        int r = m0 + mt*16 + arow;
        ldsm4(a[mt][0],a[mt][1],a[mt][2],a[mt][3], sA + r*128 + ((acg ^ (r&7))<<4));
    }
    int brow_off = (lane & 7) + ((lane>>4)<<3);
    int bcg = (k0>>3) + ((lane>>3)&1);
#pragma unroll
    for (int nt = 0; nt < NT; nt += 2) {
        int r = n0 + nt*8 + brow_off;
        unsigned b[4];
        ldsm4(b[0],b[1],b[2],b[3], sB + r*128 + ((bcg ^ (r&7))<<4));
#pragma unroll
        for (int mt = 0; mt < MT; mt++) {
            mma_bf16(acc[mt][nt],   a[mt], b);
            mma_bf16(acc[mt][nt+1], a[mt], b+2);
        }
    }
}

// warp k16-step with transposed B: B buffer 256B rows [k64][n128]
template<int MT,int NT>
__device__ __forceinline__ void wstep_t(float (&acc)[MT][NT][4], unsigned sA, unsigned sB,
                                        int m0, int n0, int k0, int lane)
{
    unsigned a[MT][4];
    int arow = lane & 15, acg = (k0>>3) + (lane>>4);
#pragma unroll
    for (int mt = 0; mt < MT; mt++) {
        int r = m0 + mt*16 + arow;
        ldsm4(a[mt][0],a[mt][1],a[mt][2],a[mt][3], sA + r*128 + ((acg ^ (r&7))<<4));
    }
    int brow = k0 + (lane & 7) + (((lane>>3)&1)<<3);
    int bcg_off = lane >> 4;
#pragma unroll
    for (int nt = 0; nt < NT; nt += 2) {
        int cg = ((n0 + nt*8) >> 3) + bcg_off;
        unsigned b[4];
        ldsm4t(b[0],b[1],b[2],b[3], sB + brow*256 + ((cg ^ (brow&7))<<4));
#pragma unroll
        for (int mt = 0; mt < MT; mt++) {
            mma_bf16(acc[mt][nt],   a[mt], b);
            mma_bf16(acc[mt][nt+1], a[mt], b+2);
        }
    }
}

// -------- kernel A: LN(pair rows) + q/k/v/gate projections (bf16 MMA) --------
// 256 threads = 8 warps (4m x 2n, each 64x64). M-tile 256 rows, N=128, K=128.
__global__ void __launch_bounds__(256) proj_kernel(
    const float* __restrict__ pair, const float* __restrict__ lng, const float* __restrict__ lnb,
    const float* __restrict__ Wq, const float* __restrict__ Wk, const float* __restrict__ Wv,
    const float* __restrict__ Wg, const float* __restrict__ bg)
{
    extern __shared__ unsigned char sm[];
    // sm[0..65536): X tile, 2 k-chunks x (256 rows x 128B)
    // sm[65536..81920): W chunk (128 rows x 128B)
    unsigned sXa = (unsigned)__cvta_generic_to_shared(sm);
    unsigned sWa = sXa + 65536;
    int tid = threadIdx.x, lane = tid & 31, warp = tid >> 5;
    int wm = warp >> 1, wn = warp & 1;
    int row0 = blockIdx.x * 256;

    // ---- LayerNorm: one thread per row; rows are p[n,i] = pair[i,n] ----
    {
        int r = tid;
        int row = row0 + r;
        int n = row / LREF, i = row - n*LREF;
        const float* x = pair + ((size_t)i*LREF + n) * DPC;
        float s = 0.f, s2 = 0.f;
#pragma unroll 8
        for (int c = 0; c < DPC; c += 4) {
            float4 t = *(const float4*)(x + c);
            s  += t.x + t.y + t.z + t.w;
            s2 += t.x*t.x + t.y*t.y + t.z*t.z + t.w*t.w;
        }
        float mean = s * (1.f/DPC);
        float rstd = rsqrtf(s2 * (1.f/DPC) - mean*mean + 1e-5f);
#pragma unroll
        for (int g = 0; g < 16; g++) {
            float4 t0 = *(const float4*)(x + g*8);
            float4 t1 = *(const float4*)(x + g*8 + 4);
            float4 w0 = *(const float4*)(lng + g*8);
            float4 w1 = *(const float4*)(lng + g*8 + 4);
            float4 b0 = *(const float4*)(lnb + g*8);
            float4 b1 = *(const float4*)(lnb + g*8 + 4);
            uint4 o;
            o.x = pk2((t0.x-mean)*rstd*w0.x + b0.x, (t0.y-mean)*rstd*w0.y + b0.y);
            o.y = pk2((t0.z-mean)*rstd*w0.z + b0.z, (t0.w-mean)*rstd*w0.w + b0.w);
            o.z = pk2((t1.x-mean)*rstd*w1.x + b1.x, (t1.y-mean)*rstd*w1.y + b1.y);
            o.w = pk2((t1.z-mean)*rstd*w1.z + b1.z, (t1.w-mean)*rstd*w1.w + b1.w);
            int kc = g >> 3, gg = g & 7;
            *(uint4*)(sm + kc*32768 + r*128 + ((gg ^ (r&7))<<4)) = o;
        }
    }
    __syncthreads();

    const float* Ws[4] = { Wq, Wk, Wv, Wg };
    for (int mat = 0; mat < 4; mat++) {
        float acc[4][8][4];
#pragma unroll
        for (int a = 0; a < 4; a++)
#pragma unroll
            for (int b = 0; b < 8; b++)
#pragma unroll
                for (int cc = 0; cc < 4; cc++) acc[a][b][cc] = 0.f;

        const float* W = Ws[mat];
        for (int kc = 0; kc < 2; kc++) {
            __syncthreads();
            for (int c = tid; c < 1024; c += 256) {
                int r = c >> 3, g = c & 7;
                const float* src = W + (size_t)r*DPC + kc*64 + g*8;
                float4 t0 = *(const float4*)src;
                float4 t1 = *(const float4*)(src + 4);
                uint4 o;
                o.x = pk2(t0.x, t0.y); o.y = pk2(t0.z, t0.w);
                o.z = pk2(t1.x, t1.y); o.w = pk2(t1.z, t1.w);
                *(uint4*)(sm + 65536 + r*128 + ((g ^ (r&7))<<4)) = o;
            }
            __syncthreads();
#pragma unroll
            for (int kk = 0; kk < 4; kk++)
                wstep<4,8>(acc, sXa + kc*32768, sWa, wm*64, wn*64, kk*16, lane);
        }

        float scale = (mat == 0) ? 0.17677669529663687f : (mat == 1 ? (1.0f/LREF) : 1.0f);
#pragma unroll
        for (int mt = 0; mt < 4; mt++)
#pragma unroll
            for (int nt = 0; nt < 8; nt++) {
                float* ac = acc[mt][nt];
                int rl = wm*64 + mt*16 + (lane >> 2);
                int c  = wn*64 + nt*8 + 2*(lane & 3);
                int h = c >> 5, d = c & 31;
#pragma unroll
                for (int half = 0; half < 2; half++) {
                    int row = row0 + rl + half*8;
                    float v0 = ac[half*2+0], v1 = ac[half*2+1];
                    int n = row / LREF, i = row - n*LREF;
                    size_t qidx = ((size_t)(h*LREF + i))*KTOT + n*DHD + d;
                    if (mat == 0) {
                        *(bf162*)&g_qb[qidx] = __floats2bfloat162_rn(v0*scale, v1*scale);
                    } else if (mat == 1) {
                        *(bf162*)&g_kb[qidx] = __floats2bfloat162_rn(v0*scale, v1*scale);
                    } else if (mat == 2) {
                        *(bf162*)&g_vb[qidx] = __floats2bfloat162_rn(v0, v1);
                    } else {
                        float z0 = v0 + bg[c], z1 = v1 + bg[c+1];
                        *(bf162*)&g_gateb[(size_t)row*DPC + c] =
                            __floats2bfloat162_rn(1.f/(1.f+expf(-z0)), 1.f/(1.f+expf(-z1)));
                    }
                }
            }
    }
}

// -------- kernel B: LN(bias rows) @ Wb^T -> init fp32 attn -------------------
__global__ void __launch_bounds__(128) bias_kernel(
    const float* __restrict__ bias, const float* __restrict__ lng, const float* __restrict__ lnb,
    const float* __restrict__ Wb)
{
    __shared__ float sx[16][DPC];
    int tid = threadIdx.x, warp = tid >> 5, lane = tid & 31;
    int row0 = blockIdx.x * 16;                 // row = i*L + j

    for (int rr = 0; rr < 4; rr++) {
        int r = warp * 4 + rr;
        int row = row0 + r;
        int i = row / LREF, j = row % LREF;
        const float* x = bias + ((size_t)j * LREF + i) * DPC;
        float v0 = x[lane], v1 = x[lane+32], v2 = x[lane+64], v3 = x[lane+96];
        float s = v0 + v1 + v2 + v3;
#pragma unroll
        for (int o = 16; o; o >>= 1) s += __shfl_xor_sync(0xffffffffu, s, o);
        float mean = s * (1.f / DPC);
        float d0 = v0-mean, d1 = v1-mean, d2 = v2-mean, d3 = v3-mean;
        float ss = d0*d0 + d1*d1 + d2*d2 + d3*d3;
#pragma unroll
        for (int o = 16; o; o >>= 1) ss += __shfl_xor_sync(0xffffffffu, ss, o);
        float rstd = rsqrtf(ss * (1.f / DPC) + 1e-5f);
        sx[r][lane]    = d0 * rstd * lng[lane]    + lnb[lane];
        sx[r][lane+32] = d1 * rstd * lng[lane+32] + lnb[lane+32];
        sx[r][lane+64] = d2 * rstd * lng[lane+64] + lnb[lane+64];
        sx[r][lane+96] = d3 * rstd * lng[lane+96] + lnb[lane+96];
    }
    __syncthreads();

    if (tid < 64) {
        int r = tid >> 2, h = tid & 3;
        int row = row0 + r;
        int i = row / LREF, j = row % LREF;
        const float* wrow = Wb + h * DPC;
        float acc = 0.f;
#pragma unroll
        for (int c = 0; c < DPC; c += 4) {
            float4 xv = *(const float4*)(&sx[r][c]);
            float4 wv = *(const float4*)(wrow + c);
            acc += xv.x*wv.x + xv.y*wv.y + xv.z*wv.z + xv.w*wv.w;
        }
        g_attn[((size_t)h * LREF + i) * LREF + j] = acc;
    }
}

// -------- kernel C: attn += q.k  (128x128 tiles, split-K 4, bf16 MMA) --------
__global__ void __launch_bounds__(256) score_kernel()
{
    extern __shared__ unsigned char sm[];
    unsigned sA = (unsigned)__cvta_generic_to_shared(sm);     // 2 x 16KB
    unsigned sB = sA + 32768;                                 // 2 x 16KB
    int tid = threadIdx.x, lane = tid & 31, warp = tid >> 5;
    int wm = warp & 3, wn = warp >> 2;
    int h = blockIdx.z >> 2, ks = blockIdx.z & 3;
    int i0 = blockIdx.x * 128, j0 = blockIdx.y * 128;

    const bf16* ga = g_qb + ((size_t)(h*LREF + i0))*KTOT + ks*(KTOT/4);
    const bf16* gb = g_kb + ((size_t)(h*LREF + j0))*KTOT + ks*(KTOT/4);

    float acc[2][8][4];
#pragma unroll
    for (int a = 0; a < 2; a++)
#pragma unroll
        for (int b = 0; b < 8; b++)
#pragma unroll
            for (int cc = 0; cc < 4; cc++) acc[a][b][cc] = 0.f;

    const int NIT = (KTOT/4)/64;   // 48
    auto stage = [&](int it) {
        unsigned off = (it & 1) * 16384;
        for (int c = tid; c < 1024; c += 256) {
            int r = c >> 3, g = c & 7;
            unsigned d = r*128 + ((g ^ (r&7))<<4);
            cpa16(sA + off + d, ga + (size_t)r*KTOT + it*64 + g*8);
            cpa16(sB + off + d, gb + (size_t)r*KTOT + it*64 + g*8);
        }
        cpa_commit();
    };
    stage(0);
    for (int it = 0; it < NIT; it++) {
        if (it + 1 < NIT) { stage(it + 1); cpa_wait<1>(); }
        else cpa_wait<0>();
        __syncthreads();
        unsigned off = (it & 1) * 16384;
#pragma unroll
        for (int kk = 0; kk < 4; kk++)
            wstep<2,8>(acc, sA + off, sB + off, wm*32, wn*64, kk*16, lane);
        __syncthreads();
    }

#pragma unroll
    for (int mt = 0; mt < 2; mt++)
#pragma unroll
        for (int nt = 0; nt < 8; nt++) {
            float* ac = acc[mt][nt];
            int r = i0 + wm*32 + mt*16 + (lane >> 2);
            int c = j0 + wn*64 + nt*8 + 2*(lane & 3);
            size_t base = ((size_t)h*LREF + r)*LREF + c;
            atomicAdd(&g_attn[base],            ac[0]);
            atomicAdd(&g_attn[base + 1],        ac[1]);
            atomicAdd(&g_attn[base + 8*LREF],   ac[2]);
            atomicAdd(&g_attn[base + 8*LREF+1], ac[3]);
        }
}

// -------- softmax over j per (h,i): fp32 in, bf16 out ------------------------
__global__ void __launch_bounds__(128) softmax_kernel()
{
    int i = blockIdx.x, h = blockIdx.y;
    const float* row = g_attn + ((size_t)h * LREF + i) * LREF;
    bf16* orow = g_attnb + ((size_t)h * LREF + i) * LREF;
    int tid = threadIdx.x, warp = tid >> 5, lane = tid & 31;
    __shared__ float smax[4], ssum[4];

    float a0 = row[tid], a1 = row[tid + 128], a2 = row[tid + 256];
    float m = fmaxf(a0, fmaxf(a1, a2));
#pragma unroll
    for (int o = 16; o; o >>= 1) m = fmaxf(m, __shfl_xor_sync(0xffffffffu, m, o));
    if (lane == 0) smax[warp] = m;
    __syncthreads();
    float M = fmaxf(fmaxf(smax[0], smax[1]), fmaxf(smax[2], smax[3]));

    float e0 = expf(a0 - M), e1 = expf(a1 - M), e2 = expf(a2 - M);
    float s = e0 + e1 + e2;
#pragma unroll
    for (int o = 16; o; o >>= 1) s += __shfl_xor_sync(0xffffffffu, s, o);
    if (lane == 0) ssum[warp] = s;
    __syncthreads();
    float S = ssum[0] + ssum[1] + ssum[2] + ssum[3];
    float inv = 1.f / S;
    orow[tid]       = __float2bfloat16_rn(e0 * inv);
    orow[tid + 128] = __float2bfloat16_rn(e1 * inv);
    orow[tid + 256] = __float2bfloat16_rn(e2 * inv);
}

// -------- kernel D: om[n*L+i][h*32+d] = attn_b[h] @ v  (trans-B MMA) ---------
__global__ void __launch_bounds__(256) av_kernel()
{
    extern __shared__ unsigned char sm[];
    unsigned sA = (unsigned)__cvta_generic_to_shared(sm);     // 2 x 16KB (128x64 rows 128B)
    unsigned sB = sA + 32768;                                 // 2 x 16KB (64x128 rows 256B)
    int tid = threadIdx.x, lane = tid & 31, warp = tid >> 5;
    int wm = warp & 3, wn = warp >> 2;
    int i0 = blockIdx.x * 128, col0 = blockIdx.y * 128, h = blockIdx.z;

    const bf16* ga = g_attnb + ((size_t)(h*LREF + i0))*LREF;
    const bf16* gv = g_vb + (size_t)h*LREF*KTOT + col0;

    float acc[2][8][4];
#pragma unroll
    for (int a = 0; a < 2; a++)
#pragma unroll
        for (int b = 0; b < 8; b++)
#pragma unroll
            for (int cc = 0; cc < 4; cc++) acc[a][b][cc] = 0.f;

    const int NIT = LREF/64;   // 6
    auto stage = [&](int it) {
        unsigned off = (it & 1) * 16384;
        for (int c = tid; c < 1024; c += 256) {
            int ra = c >> 3, gA = c & 7;
            cpa16(sA + off + ra*128 + ((gA ^ (ra&7))<<4), ga + (size_t)ra*LREF + it*64 + gA*8);
            int rb = c >> 4, gB = c & 15;
            cpa16(sB + off + rb*256 + ((gB ^ (rb&7))<<4), gv + (size_t)(it*64 + rb)*KTOT + gB*8);
        }
        cpa_commit();
    };
    stage(0);
    for (int it = 0; it < NIT; it++) {
        if (it + 1 < NIT) { stage(it + 1); cpa_wait<1>(); }
        else cpa_wait<0>();
        __syncthreads();
        unsigned off = (it & 1) * 16384;
#pragma unroll
        for (int kk = 0; kk < 4; kk++)
            wstep_t<2,8>(acc, sA + off, sB + off, wm*32, wn*64, kk*16, lane);
        __syncthreads();
    }

#pragma unroll
    for (int mt = 0; mt < 2; mt++)
#pragma unroll
        for (int nt = 0; nt < 8; nt++) {
            float* ac = acc[mt][nt];
            int c = col0 + wn*64 + nt*8 + 2*(lane & 3);
            int n = c >> 5, d = c & 31;
#pragma unroll
            for (int half = 0; half < 2; half++) {
                int i = i0 + wm*32 + mt*16 + (lane >> 2) + half*8;
                *(bf162*)&g_omb[((size_t)n*LREF + i)*DPC + h*DHD + d] =
                    __floats2bfloat162_rn(ac[half*2+0], ac[half*2+1]);
            }
        }
}

// -------- kernel E: y = (gate .* om) @ Wo^T + bo, write transposed -----------
__global__ void __launch_bounds__(256) out_kernel(
    const float* __restrict__ Wo, const float* __restrict__ bo, float* __restrict__ outp)
{
    extern __shared__ unsigned char sm[];
    unsigned sXa = (unsigned)__cvta_generic_to_shared(sm);   // 2 chunks x 32KB
    unsigned sWa = sXa + 65536;                              // 16KB
    int tid = threadIdx.x, lane = tid & 31, warp = tid >> 5;
    int wm = warp >> 1, wn = warp & 1;
    int row0 = blockIdx.x * 256;

    {
        int r = tid;
        size_t grow = (size_t)(row0 + r) * DPC;
#pragma unroll
        for (int g = 0; g < 16; g++) {
            uint4 gt = *(const uint4*)&g_gateb[grow + g*8];
            uint4 ot = *(const uint4*)&g_omb[grow + g*8];
            uint4 o;
            ((bf162*)&o)[0] = __hmul2(((bf162*)&gt)[0], ((bf162*)&ot)[0]);
            ((bf162*)&o)[1] = __hmul2(((bf162*)&gt)[1], ((bf162*)&ot)[1]);
            ((bf162*)&o)[2] = __hmul2(((bf162*)&gt)[2], ((bf162*)&ot)[2]);
            ((bf162*)&o)[3] = __hmul2(((bf162*)&gt)[3], ((bf162*)&ot)[3]);
            int kc = g >> 3, gg = g & 7;
            *(uint4*)(sm + kc*32768 + r*128 + ((gg ^ (r&7))<<4)) = o;
        }
    }
    __syncthreads();

    float acc[4][8][4];
#pragma unroll
    for (int a = 0; a < 4; a++)
#pragma unroll
        for (int b = 0; b < 8; b++)
#pragma unroll
            for (int cc = 0; cc < 4; cc++) acc[a][b][cc] = 0.f;

    for (int kc = 0; kc < 2; kc++) {
        __syncthreads();
        for (int c = tid; c < 1024; c += 256) {
            int r = c >> 3, g = c & 7;
            const float* src = Wo + (size_t)r*DPC + kc*64 + g*8;
            float4 t0 = *(const float4*)src;
            float4 t1 = *(const float4*)(src + 4);
            uint4 o;
            o.x = pk2(t0.x, t0.y); o.y = pk2(t0.z, t0.w);
            o.z = pk2(t1.x, t1.y); o.w = pk2(t1.z, t1.w);
            *(uint4*)(sm + 65536 + r*128 + ((g ^ (r&7))<<4)) = o;
        }
        __syncthreads();
#pragma unroll
        for (int kk = 0; kk < 4; kk++)
            wstep<4,8>(acc, sXa + kc*32768, sWa, wm*64, wn*64, kk*16, lane);
    }

#pragma unroll
    for (int mt = 0; mt < 4; mt++)
#pragma unroll
        for (int nt = 0; nt < 8; nt++) {
            float* ac = acc[mt][nt];
            int rl = wm*64 + mt*16 + (lane >> 2);
            int c  = wn*64 + nt*8 + 2*(lane & 3);
            float b0 = bo[c], b1 = bo[c+1];
#pragma unroll
            for (int half = 0; half < 2; half++) {
                int row = row0 + rl + half*8;
                int n = row / LREF, i = row - n*LREF;
                *(float2*)&outp[((size_t)i*LREF + n)*DPC + c] =
                    make_float2(ac[half*2+0] + b0, ac[half*2+1] + b1);
            }
        }
}

extern "C" void kernel_launch(void* const* d_in, const int* in_sizes, int n_in,
                              void* d_out, int out_size)
{
    (void)in_sizes; (void)n_in; (void)out_size;
    const float* pair      = (const float*)d_in[0];
    const float* bias      = (const float*)d_in[1];
    const float* ln_pair_g = (const float*)d_in[2];
    const float* ln_pair_b = (const float*)d_in[3];
    const float* ln_bias_g = (const float*)d_in[4];
    const float* ln_bias_b = (const float*)d_in[5];
    const float* Wq = (const float*)d_in[6];
    const float* Wk = (const float*)d_in[7];
    const float* Wv = (const float*)d_in[8];
    const float* Wb = (const float*)d_in[9];
    const float* Wg = (const float*)d_in[10];
    const float* bg = (const float*)d_in[11];
    const float* Wo = (const float*)d_in[12];
    const float* bo = (const float*)d_in[13];
    float* outp = (float*)d_out;

    const int PROJ_SMEM = 81920;
    const int GEMM_SMEM = 65536;
    cudaFuncSetAttribute(proj_kernel,  cudaFuncAttributeMaxDynamicSharedMemorySize, PROJ_SMEM);
    cudaFuncSetAttribute(score_kernel, cudaFuncAttributeMaxDynamicSharedMemorySize, GEMM_SMEM);
    cudaFuncSetAttribute(av_kernel,    cudaFuncAttributeMaxDynamicSharedMemorySize, GEMM_SMEM);
    cudaFuncSetAttribute(out_kernel,   cudaFuncAttributeMaxDynamicSharedMemorySize, PROJ_SMEM);

    proj_kernel<<<LREF*LREF/256, 256, PROJ_SMEM>>>(pair, ln_pair_g, ln_pair_b, Wq, Wk, Wv, Wg, bg);
    bias_kernel<<<LREF*LREF/16, 128>>>(bias, ln_bias_g, ln_bias_b, Wb);
    score_kernel<<<dim3(3, 3, 16), 256, GEMM_SMEM>>>();
    softmax_kernel<<<dim3(LREF, HN), 128>>>();
    av_kernel<<<dim3(3, KTOT/128, HN), 256, GEMM_SMEM>>>();
    out_kernel<<<LREF*LREF/256, 256, PROJ_SMEM>>>(Wo, bo, outp);
}